// round 1
// baseline (speedup 1.0000x reference)
#include <cuda_runtime.h>
#include <cuda_bf16.h>
#include <math.h>

#define B_  2
#define T_  2048
#define DM  2048
#define NH  16
#define NKV 8
#define HD  128

// ---------------- scratch (device globals: no allocs allowed) ----------------
__device__ float g_Q[(size_t)B_ * T_ * NH * HD];    // [B*T, 2048]
__device__ float g_K[(size_t)B_ * T_ * NKV * HD];   // [B*T, 1024]
__device__ float g_V[(size_t)B_ * T_ * NKV * HD];   // [B*T, 1024]
__device__ float g_cos[T_ * 64];
__device__ float g_sin[T_ * 64];

// ---------------- RoPE table (bf16-rounded like the reference) ----------------
__global__ void rope_table_kernel() {
    int t = blockIdx.x;
    int i = threadIdx.x;   // 0..63
    double invf = 1.0 / pow(10000.0, (double)(2 * i) / 128.0);
    float angle = (float)t * (float)invf;          // f32 product like np.outer(f32,f32)
    float c = (float)cos((double)angle);
    float s = (float)sin((double)angle);
    g_cos[t * 64 + i] = __bfloat162float(__float2bfloat16(c));
    g_sin[t * 64 + i] = __bfloat162float(__float2bfloat16(s));
}

// ---------------- SGEMM: C[M,N] = A[M,K] @ B[N,K]^T (fp32) ----------------
// BM=BN=128, BK=8, 256 threads, 8x8 micro-tile per thread.
__global__ __launch_bounds__(256) void sgemm_nt(const float* __restrict__ A,
                                                const float* __restrict__ B,
                                                float* __restrict__ C,
                                                int M, int N, int K) {
    __shared__ float As[8][132];   // padded: conflict-free stores & float4 loads
    __shared__ float Bs[8][132];
    int tid = threadIdx.x;
    int tx = tid & 15, ty = tid >> 4;
    int row0 = blockIdx.y * 128, col0 = blockIdx.x * 128;

    float acc[8][8];
#pragma unroll
    for (int i = 0; i < 8; i++)
#pragma unroll
        for (int j = 0; j < 8; j++) acc[i][j] = 0.f;

    for (int k0 = 0; k0 < K; k0 += 8) {
#pragma unroll
        for (int it = 0; it < 4; it++) {
            int idx = tid + it * 256;         // 0..1023
            int m = idx >> 3, kk = idx & 7;
            As[kk][m] = A[(size_t)(row0 + m) * K + k0 + kk];
            Bs[kk][m] = B[(size_t)(col0 + m) * K + k0 + kk];
        }
        __syncthreads();
#pragma unroll
        for (int kk = 0; kk < 8; kk++) {
            float4 a0 = *(const float4*)&As[kk][ty * 4];
            float4 a1 = *(const float4*)&As[kk][64 + ty * 4];
            float4 b0 = *(const float4*)&Bs[kk][tx * 4];
            float4 b1 = *(const float4*)&Bs[kk][64 + tx * 4];
            float ra[8] = {a0.x, a0.y, a0.z, a0.w, a1.x, a1.y, a1.z, a1.w};
            float rb[8] = {b0.x, b0.y, b0.z, b0.w, b1.x, b1.y, b1.z, b1.w};
#pragma unroll
            for (int i = 0; i < 8; i++)
#pragma unroll
                for (int j = 0; j < 8; j++)
                    acc[i][j] = fmaf(ra[i], rb[j], acc[i][j]);
        }
        __syncthreads();
    }
#pragma unroll
    for (int i = 0; i < 8; i++) {
        int r = row0 + ((i < 4) ? ty * 4 + i : 64 + ty * 4 + (i - 4));
#pragma unroll
        for (int j = 0; j < 8; j++) {
            int c = col0 + ((j < 4) ? tx * 4 + j : 64 + tx * 4 + (j - 4));
            C[(size_t)r * N + c] = acc[i][j];
        }
    }
}

// ---------------- RMS-norm + RoPE + q scaling (in place) ----------------
// One warp per (b,t,head) row of 128 values. h<16 -> Q row, h>=16 -> K row.
__global__ __launch_bounds__(256) void postproc_kernel(const float* __restrict__ scaler) {
    int gw = blockIdx.x * 8 + (threadIdx.x >> 5);
    int lane = threadIdx.x & 31;
    int r = gw / 24;
    int h = gw - r * 24;
    int t = r & (T_ - 1);
    float* base;
    if (h < 16) base = g_Q + (size_t)r * 2048 + h * 128;
    else        base = g_K + (size_t)r * 1024 + (h - 16) * 128;

    float x0 = base[lane], x1 = base[lane + 32], x2 = base[lane + 64], x3 = base[lane + 96];
    float ss = x0 * x0 + x1 * x1 + x2 * x2 + x3 * x3;
#pragma unroll
    for (int o = 16; o; o >>= 1) ss += __shfl_xor_sync(0xffffffffu, ss, o);
    float rn = rsqrtf(ss * (1.0f / 128.0f) + 1.1920929e-07f);   // eps = finfo(f32).eps
    x0 *= rn; x1 *= rn; x2 *= rn; x3 *= rn;

    // RoPE pairs: (d, d+64) for d<64. lane handles d=lane and d=lane+32.
    float c0 = g_cos[t * 64 + lane],      s0 = g_sin[t * 64 + lane];
    float c1 = g_cos[t * 64 + lane + 32], s1 = g_sin[t * 64 + lane + 32];
    float o0 =  x0 * c0 + x2 * s0;
    float o2 = -x0 * s0 + x2 * c0;
    float o1 =  x1 * c1 + x3 * s1;
    float o3 = -x1 * s1 + x3 * c1;
    if (h < 16) {
        float sc = scaler[h] * logf((float)(t + 1));
        o0 *= sc; o1 *= sc; o2 *= sc; o3 *= sc;
    }
    base[lane] = o0; base[lane + 32] = o1; base[lane + 64] = o2; base[lane + 96] = o3;
}

// ---------------- differential causal flash attention ----------------
struct AttnSmem {
    float Qs[16][128];    // [y*8+qi][d], pre-scaled by 1/sqrt(128)
    float K1s[32][132];   // padded rows: conflict-free lane-owns-key reads
    float K2s[32][132];
    float Vs[32][256];
    float O1s[8][256];
    float lam;
};

__global__ __launch_bounds__(512) void diff_attn_kernel(
    const float* __restrict__ lq1, const float* __restrict__ lk1,
    const float* __restrict__ lq2, const float* __restrict__ lk2,
    float* __restrict__ out) {
    extern __shared__ char smem_raw[];
    AttnSmem* S = (AttnSmem*)smem_raw;
    int tid = threadIdx.x;
    int warp = tid >> 5, lane = tid & 31;
    int y = warp >> 3;        // 0: y1 branch, 1: y2 branch
    int qi = warp & 7;        // query within block
    int qblk = blockIdx.x, h = blockIdx.y, b = blockIdx.z;
    int q = qblk * 8 + qi;

    if (tid == 0) {
        float s1 = 0.f, s2 = 0.f;
        for (int i = 0; i < 64; i++) { s1 += lq1[i] * lk1[i]; s2 += lq2[i] * lk2[i]; }
        S->lam = expf(s1) - expf(s2) + 0.2f;
    }
    const float SCALE = 0.08838834764831845f;   // 1/sqrt(128)
    for (int i = tid; i < 16 * 128; i += 512) {
        int rr = i >> 7, d = i & 127;
        int yy = rr >> 3, qq = rr & 7;
        S->Qs[rr][d] = g_Q[(size_t)(b * T_ + qblk * 8 + qq) * 2048 + (yy * 8 + h) * 128 + d] * SCALE;
    }

    int hk1 = (h >> 1) * 128;         // k1 = kv heads 0..3, repeat by 2
    int hk2 = 512 + (h >> 1) * 128;   // k2 = kv heads 4..7
    int vcol = (h >> 1) * 256;        // v head = contiguous 256 cols
    const float* Kb = g_K + (size_t)b * T_ * 1024;
    const float* Vb = g_V + (size_t)b * T_ * 1024;

    float m = -INFINITY, l = 0.f;
    float o[8];
#pragma unroll
    for (int i = 0; i < 8; i++) o[i] = 0.f;

    int ntiles = (qblk * 8 + 7) / 32 + 1;
    for (int kt = 0; kt < ntiles; kt++) {
        __syncthreads();
        int base_row = kt * 32;
#pragma unroll
        for (int it = 0; it < 2; it++) {
            int f4 = tid + it * 512;
            int j = f4 >> 5, c4 = f4 & 31;
            const float* krow = &Kb[(size_t)(base_row + j) * 1024];
            *(float4*)&S->K1s[j][c4 * 4] = *(const float4*)&krow[hk1 + c4 * 4];
            *(float4*)&S->K2s[j][c4 * 4] = *(const float4*)&krow[hk2 + c4 * 4];
        }
#pragma unroll
        for (int it = 0; it < 4; it++) {
            int f4 = tid + it * 512;
            int j = f4 >> 6, c4 = f4 & 63;
            *(float4*)&S->Vs[j][c4 * 4] =
                *(const float4*)&Vb[(size_t)(base_row + j) * 1024 + vcol + c4 * 4];
        }
        __syncthreads();

        // S = q . k  — lane owns key j=lane; q broadcast from smem (conflict-free)
        const float* Ks = y ? &S->K2s[0][0] : &S->K1s[0][0];
        const float* qrow = &S->Qs[y * 8 + qi][0];
        float s = 0.f;
#pragma unroll
        for (int d4 = 0; d4 < 32; d4++) {
            float4 qv = *(const float4*)&qrow[d4 * 4];
            float4 kv = *(const float4*)&Ks[lane * 132 + d4 * 4];
            s = fmaf(qv.x, kv.x, fmaf(qv.y, kv.y, fmaf(qv.z, kv.z, fmaf(qv.w, kv.w, s))));
        }
        bool valid = (base_row + lane) <= q;
        float sv = valid ? s : -INFINITY;
        float tmax = sv;
#pragma unroll
        for (int off = 16; off; off >>= 1)
            tmax = fmaxf(tmax, __shfl_xor_sync(0xffffffffu, tmax, off));
        float mnew = fmaxf(m, tmax);          // finite after tile 0 (key 0 always valid)
        float alpha = expf(m - mnew);         // first tile: expf(-inf)=0
        float p = valid ? expf(s - mnew) : 0.f;
        float psum = p;
#pragma unroll
        for (int off = 16; off; off >>= 1)
            psum += __shfl_xor_sync(0xffffffffu, psum, off);
        l = l * alpha + psum;
        m = mnew;
#pragma unroll
        for (int i = 0; i < 8; i++) o[i] *= alpha;
        // P @ V — lane owns dims {lane*4..+3, 128+lane*4..+3}
#pragma unroll
        for (int j = 0; j < 32; j++) {
            float pj = __shfl_sync(0xffffffffu, p, j);
            float4 v0 = *(const float4*)&S->Vs[j][lane * 4];
            float4 v1 = *(const float4*)&S->Vs[j][128 + lane * 4];
            o[0] = fmaf(pj, v0.x, o[0]); o[1] = fmaf(pj, v0.y, o[1]);
            o[2] = fmaf(pj, v0.z, o[2]); o[3] = fmaf(pj, v0.w, o[3]);
            o[4] = fmaf(pj, v1.x, o[4]); o[5] = fmaf(pj, v1.y, o[5]);
            o[6] = fmaf(pj, v1.z, o[6]); o[7] = fmaf(pj, v1.w, o[7]);
        }
    }

    float invl = 1.0f / l;
#pragma unroll
    for (int i = 0; i < 8; i++) o[i] *= invl;

    __syncthreads();
    if (y == 0) {
        float4 w0 = {o[0], o[1], o[2], o[3]}, w1 = {o[4], o[5], o[6], o[7]};
        *(float4*)&S->O1s[qi][lane * 4] = w0;
        *(float4*)&S->O1s[qi][128 + lane * 4] = w1;
    }
    __syncthreads();
    if (y == 1) {
        float lam = S->lam;
        float4 a0 = *(const float4*)&S->O1s[qi][lane * 4];
        float4 a1 = *(const float4*)&S->O1s[qi][128 + lane * 4];
        size_t ob = ((size_t)((b * T_ + q) * 8 + h)) * 256;
        float4 r0 = {a0.x - lam * o[0], a0.y - lam * o[1], a0.z - lam * o[2], a0.w - lam * o[3]};
        float4 r1 = {a1.x - lam * o[4], a1.y - lam * o[5], a1.z - lam * o[6], a1.w - lam * o[7]};
        *(float4*)&out[ob + lane * 4] = r0;
        *(float4*)&out[ob + 128 + lane * 4] = r1;
    }
}

// ---------------- launch ----------------
extern "C" void kernel_launch(void* const* d_in, const int* in_sizes, int n_in,
                              void* d_out, int out_size) {
    const float* x      = (const float*)d_in[0];
    const float* Wq     = (const float*)d_in[1];
    const float* Wk     = (const float*)d_in[2];
    const float* Wv     = (const float*)d_in[3];
    const float* lq1    = (const float*)d_in[4];
    const float* lk1    = (const float*)d_in[5];
    const float* lq2    = (const float*)d_in[6];
    const float* lk2    = (const float*)d_in[7];
    const float* scaler = (const float*)d_in[8];
    float* out = (float*)d_out;

    float *qptr, *kptr, *vptr;
    cudaGetSymbolAddress((void**)&qptr, g_Q);
    cudaGetSymbolAddress((void**)&kptr, g_K);
    cudaGetSymbolAddress((void**)&vptr, g_V);

    rope_table_kernel<<<T_, 64>>>();

    sgemm_nt<<<dim3(16, 32), 256>>>(x, Wq, qptr, B_ * T_, 2048, 2048);
    sgemm_nt<<<dim3(8, 32),  256>>>(x, Wk, kptr, B_ * T_, 1024, 2048);
    sgemm_nt<<<dim3(8, 32),  256>>>(x, Wv, vptr, B_ * T_, 1024, 2048);

    postproc_kernel<<<(B_ * T_ * 24) / 8, 256>>>(scaler);

    cudaFuncSetAttribute(diff_attn_kernel, cudaFuncAttributeMaxDynamicSharedMemorySize,
                         (int)sizeof(AttnSmem));
    diff_attn_kernel<<<dim3(T_ / 8, 8, B_), 512, sizeof(AttnSmem)>>>(lq1, lk1, lq2, lk2, out);
}

// round 2
// speedup vs baseline: 1.8300x; 1.8300x over previous
#include <cuda_runtime.h>
#include <cuda_bf16.h>
#include <math.h>

#define B_  2
#define T_  2048
#define DM  2048

// ---------------- scratch ----------------
__device__ float g_Q[(size_t)B_ * T_ * 2048];                 // gemm out [B*T, 2048]
__device__ float g_K[(size_t)B_ * T_ * 1024];                 // gemm out [B*T, 1024]
__device__ float g_V[(size_t)B_ * T_ * 1024];                 // [b][t][vh*256+vd]
__device__ float g_Qt[(size_t)B_ * 2 * 8 * 128 * T_];         // [b][y][h][d][t]
__device__ float g_Kt[(size_t)B_ * 2 * 4 * 128 * T_];         // [b][y][kh][d][t]
__device__ float g_cos[T_ * 64];
__device__ float g_sin[T_ * 64];
__device__ float g_lam;

// ---------------- RoPE table (bf16-rounded) + lambda ----------------
__global__ void rope_lam_kernel(const float* __restrict__ lq1, const float* __restrict__ lk1,
                                const float* __restrict__ lq2, const float* __restrict__ lk2) {
    int t = blockIdx.x;
    int i = threadIdx.x;   // 0..63
    double invf = 1.0 / pow(10000.0, (double)(2 * i) / 128.0);
    float angle = (float)t * (float)invf;
    g_cos[t * 64 + i] = __bfloat162float(__float2bfloat16((float)cos((double)angle)));
    g_sin[t * 64 + i] = __bfloat162float(__float2bfloat16((float)sin((double)angle)));
    if (t == 0 && i == 0) {
        float s1 = 0.f, s2 = 0.f;
        for (int j = 0; j < 64; j++) { s1 += lq1[j] * lk1[j]; s2 += lq2[j] * lk2[j]; }
        g_lam = expf(s1) - expf(s2) + 0.2f;
    }
}

// ---------------- fused QKV SGEMM, double-buffered ----------------
// C[M,N] = A[M,K] @ W[N,K]^T. One launch: blocks 0..511 Q, 512..767 K, 768..1023 V.
__global__ __launch_bounds__(256) void qkv_gemm(const float* __restrict__ x,
                                                const float* __restrict__ Wq,
                                                const float* __restrict__ Wk,
                                                const float* __restrict__ Wv) {
    __shared__ float As[2][8][132];
    __shared__ float Bs[2][8][132];
    int bid = blockIdx.x;
    const float* Bw; float* C; int N, bx, by;
    if (bid < 512)      { Bw = Wq; C = g_Q; N = 2048; bx = bid & 15; by = bid >> 4; }
    else if (bid < 768) { int u = bid - 512; Bw = Wk; C = g_K; N = 1024; bx = u & 7; by = u >> 3; }
    else                { int u = bid - 768; Bw = Wv; C = g_V; N = 1024; bx = u & 7; by = u >> 3; }
    const int K = 2048;
    int tid = threadIdx.x;
    int tx = tid & 15, ty = tid >> 4;
    int row0 = by * 128, col0 = bx * 128;

    float acc[8][8];
#pragma unroll
    for (int i = 0; i < 8; i++)
#pragma unroll
        for (int j = 0; j < 8; j++) acc[i][j] = 0.f;

    float la[4], lb[4];
#pragma unroll
    for (int it = 0; it < 4; it++) {
        int idx = tid + it * 256; int m = idx >> 3, kk = idx & 7;
        la[it] = x [(size_t)(row0 + m) * K + kk];
        lb[it] = Bw[(size_t)(col0 + m) * K + kk];
    }
#pragma unroll
    for (int it = 0; it < 4; it++) {
        int idx = tid + it * 256; int m = idx >> 3, kk = idx & 7;
        As[0][kk][m] = la[it]; Bs[0][kk][m] = lb[it];
    }
    __syncthreads();
    int buf = 0;
    for (int k0 = 0; k0 < K; k0 += 8) {
        if (k0 + 8 < K) {
#pragma unroll
            for (int it = 0; it < 4; it++) {
                int idx = tid + it * 256; int m = idx >> 3, kk = idx & 7;
                la[it] = x [(size_t)(row0 + m) * K + k0 + 8 + kk];
                lb[it] = Bw[(size_t)(col0 + m) * K + k0 + 8 + kk];
            }
        }
#pragma unroll
        for (int kk = 0; kk < 8; kk++) {
            float4 a0 = *(const float4*)&As[buf][kk][ty * 4];
            float4 a1 = *(const float4*)&As[buf][kk][64 + ty * 4];
            float4 b0 = *(const float4*)&Bs[buf][kk][tx * 4];
            float4 b1 = *(const float4*)&Bs[buf][kk][64 + tx * 4];
            float ra[8] = {a0.x, a0.y, a0.z, a0.w, a1.x, a1.y, a1.z, a1.w};
            float rb[8] = {b0.x, b0.y, b0.z, b0.w, b1.x, b1.y, b1.z, b1.w};
#pragma unroll
            for (int i = 0; i < 8; i++)
#pragma unroll
                for (int j = 0; j < 8; j++)
                    acc[i][j] = fmaf(ra[i], rb[j], acc[i][j]);
        }
        if (k0 + 8 < K) {
#pragma unroll
            for (int it = 0; it < 4; it++) {
                int idx = tid + it * 256; int m = idx >> 3, kk = idx & 7;
                As[buf ^ 1][kk][m] = la[it]; Bs[buf ^ 1][kk][m] = lb[it];
            }
            __syncthreads();
            buf ^= 1;
        }
    }
#pragma unroll
    for (int i = 0; i < 8; i++) {
        int r = row0 + ((i < 4) ? ty * 4 + i : 64 + ty * 4 + (i - 4));
#pragma unroll
        for (int j = 0; j < 8; j++) {
            int c = col0 + ((j < 4) ? tx * 4 + j : 64 + tx * 4 + (j - 4));
            C[(size_t)r * N + c] = acc[i][j];
        }
    }
}

// ---------------- RMS-norm + RoPE + q scaling, write TRANSPOSED layouts ----------------
// grid (64 token-blocks, 24 heads, B). 256 threads, warp handles 4 token rows.
__global__ __launch_bounds__(256) void postproc_kernel(const float* __restrict__ scaler) {
    __shared__ float tr[128][33];
    int tb = blockIdx.x, hsel = blockIdx.y, b = blockIdx.z;
    int warp = threadIdx.x >> 5, lane = threadIdx.x & 31;
    const float SCALE = 0.08838834764831845f;

    for (int j = 0; j < 4; j++) {
        int trow = warp * 4 + j;
        int t = tb * 32 + trow;
        size_t r = (size_t)b * T_ + t;
        const float* base = (hsel < 16) ? g_Q + r * 2048 + hsel * 128
                                        : g_K + r * 1024 + (hsel - 16) * 128;
        float x0 = base[lane], x1 = base[lane + 32], x2 = base[lane + 64], x3 = base[lane + 96];
        float ss = x0 * x0 + x1 * x1 + x2 * x2 + x3 * x3;
#pragma unroll
        for (int o = 16; o; o >>= 1) ss += __shfl_xor_sync(0xffffffffu, ss, o);
        float rn = rsqrtf(ss * (1.0f / 128.0f) + 1.1920929e-07f);
        x0 *= rn; x1 *= rn; x2 *= rn; x3 *= rn;
        float c0 = g_cos[t * 64 + lane],      s0 = g_sin[t * 64 + lane];
        float c1 = g_cos[t * 64 + lane + 32], s1 = g_sin[t * 64 + lane + 32];
        float o0 =  x0 * c0 + x2 * s0;
        float o2 = -x0 * s0 + x2 * c0;
        float o1 =  x1 * c1 + x3 * s1;
        float o3 = -x1 * s1 + x3 * c1;
        if (hsel < 16) {
            float sc = scaler[hsel] * logf((float)(t + 1)) * SCALE;
            o0 *= sc; o1 *= sc; o2 *= sc; o3 *= sc;
        }
        tr[lane][trow] = o0; tr[lane + 32][trow] = o1;
        tr[lane + 64][trow] = o2; tr[lane + 96][trow] = o3;
    }
    __syncthreads();
    float* dst;
    if (hsel < 16) {
        int y = hsel >> 3, hh = hsel & 7;
        dst = g_Qt + ((size_t)((b * 2 + y) * 8 + hh) * 128) * T_;
    } else {
        int kv = hsel - 16; int y = kv >> 2, kh = kv & 3;
        dst = g_Kt + ((size_t)((b * 2 + y) * 4 + kh) * 128) * T_;
    }
    for (int i = threadIdx.x; i < 4096; i += 256) {
        int d = i >> 5, t = i & 31;
        dst[(size_t)d * T_ + tb * 32 + t] = tr[d][t];
    }
}

// ---------------- differential causal flash attention (register-tiled) ----------------
struct AttnS {
    float Qt[2][128][32];    // [branch][d][q]   (pre-scaled)
    float Kt[2][128][32];    // [branch][d][k]   (reused as O1[32][256] in epilogue)
    float V [32][256];       // [k][vd]
    float P [2][32][36];     // [branch][q][k]
};

__global__ __launch_bounds__(256, 2) void diff_attn_kernel(float* __restrict__ out) {
    extern __shared__ char sraw[];
    AttnS* S = (AttnS*)sraw;
    int tid = threadIdx.x;
    int qt = (gridDim.x - 1) - blockIdx.x;   // largest tiles scheduled first
    int h = blockIdx.y, b = blockIdx.z;
    int y    = tid >> 7;          // branch
    int t128 = tid & 127;
    int txk  = t128 & 15;         // owns keys {2txk, 2txk+1}, vd cols {c*64 + 4txk ..}
    int ty   = t128 >> 4;         // owns queries {4ty .. 4ty+3}
    int q0 = qt * 32;

    const float* Qb = g_Qt + ((size_t)(b * 2 * 8 + h) * 128) * T_;          // y stride below
    const size_t QYS = (size_t)8 * 128 * T_;
    const float* Kb = g_Kt + ((size_t)(b * 2 * 4 + (h >> 1)) * 128) * T_;
    const size_t KYS = (size_t)4 * 128 * T_;
    const float* Vb = g_V + (size_t)b * T_ * 1024 + (h >> 1) * 256;

    // load Q tile once: 2048 float4
    for (int i4 = tid; i4 < 2048; i4 += 256) {
        int yy = i4 >> 10, rem = i4 & 1023;
        int d = rem >> 3, t4 = rem & 7;
        *(float4*)&S->Qt[yy][d][t4 * 4] =
            *(const float4*)(Qb + yy * QYS + (size_t)d * T_ + q0 + t4 * 4);
    }

    float m[4], l[4], o[4][16];
#pragma unroll
    for (int i = 0; i < 4; i++) {
        m[i] = -INFINITY; l[i] = 0.f;
#pragma unroll
        for (int c = 0; c < 16; c++) o[i][c] = 0.f;
    }

    for (int kt = 0; kt <= qt; kt++) {
        __syncthreads();
        int k0 = kt * 32;
        for (int i4 = tid; i4 < 2048; i4 += 256) {
            int yy = i4 >> 10, rem = i4 & 1023;
            int d = rem >> 3, t4 = rem & 7;
            *(float4*)&S->Kt[yy][d][t4 * 4] =
                *(const float4*)(Kb + yy * KYS + (size_t)d * T_ + k0 + t4 * 4);
        }
        for (int i4 = tid; i4 < 2048; i4 += 256) {
            int k = i4 >> 6, c4 = i4 & 63;
            *(float4*)&S->V[k][c4 * 4] = *(const float4*)(Vb + (size_t)(k0 + k) * 1024 + c4 * 4);
        }
        __syncthreads();

        // ---- S = Q . K^T  (per branch) ----
        float s[4][2];
#pragma unroll
        for (int i = 0; i < 4; i++) { s[i][0] = 0.f; s[i][1] = 0.f; }
#pragma unroll 8
        for (int d = 0; d < 128; d++) {
            float4 qv = *(const float4*)&S->Qt[y][d][ty * 4];
            float2 kv = *(const float2*)&S->Kt[y][d][txk * 2];
            s[0][0] = fmaf(qv.x, kv.x, s[0][0]); s[0][1] = fmaf(qv.x, kv.y, s[0][1]);
            s[1][0] = fmaf(qv.y, kv.x, s[1][0]); s[1][1] = fmaf(qv.y, kv.y, s[1][1]);
            s[2][0] = fmaf(qv.z, kv.x, s[2][0]); s[2][1] = fmaf(qv.z, kv.y, s[2][1]);
            s[3][0] = fmaf(qv.w, kv.x, s[3][0]); s[3][1] = fmaf(qv.w, kv.y, s[3][1]);
        }
        if (kt == qt) {
#pragma unroll
            for (int i = 0; i < 4; i++)
#pragma unroll
                for (int j = 0; j < 2; j++)
                    if (txk * 2 + j > ty * 4 + i) s[i][j] = -INFINITY;
        }
        // ---- online softmax ----
        float mt[4], ps[4], alpha[4];
#pragma unroll
        for (int i = 0; i < 4; i++) mt[i] = fmaxf(s[i][0], s[i][1]);
#pragma unroll
        for (int off = 8; off; off >>= 1)
#pragma unroll
            for (int i = 0; i < 4; i++)
                mt[i] = fmaxf(mt[i], __shfl_xor_sync(0xffffffffu, mt[i], off));
#pragma unroll
        for (int i = 0; i < 4; i++) {
            float mn = fmaxf(m[i], mt[i]);
            alpha[i] = __expf(m[i] - mn);
            m[i] = mn;
            s[i][0] = __expf(s[i][0] - mn);
            s[i][1] = __expf(s[i][1] - mn);
            ps[i] = s[i][0] + s[i][1];
        }
#pragma unroll
        for (int off = 8; off; off >>= 1)
#pragma unroll
            for (int i = 0; i < 4; i++)
                ps[i] += __shfl_xor_sync(0xffffffffu, ps[i], off);
#pragma unroll
        for (int i = 0; i < 4; i++) {
            l[i] = l[i] * alpha[i] + ps[i];
            *(float2*)&S->P[y][ty * 4 + i][txk * 2] = make_float2(s[i][0], s[i][1]);
#pragma unroll
            for (int c = 0; c < 16; c++) o[i][c] *= alpha[i];
        }
        __syncwarp();
        // ---- O += P . V ----
#pragma unroll 4
        for (int k = 0; k < 32; k++) {
            float p0 = S->P[y][ty * 4 + 0][k];
            float p1 = S->P[y][ty * 4 + 1][k];
            float p2 = S->P[y][ty * 4 + 2][k];
            float p3 = S->P[y][ty * 4 + 3][k];
#pragma unroll
            for (int c = 0; c < 4; c++) {
                float4 v = *(const float4*)&S->V[k][c * 64 + txk * 4];
                o[0][c*4+0] = fmaf(p0, v.x, o[0][c*4+0]); o[0][c*4+1] = fmaf(p0, v.y, o[0][c*4+1]);
                o[0][c*4+2] = fmaf(p0, v.z, o[0][c*4+2]); o[0][c*4+3] = fmaf(p0, v.w, o[0][c*4+3]);
                o[1][c*4+0] = fmaf(p1, v.x, o[1][c*4+0]); o[1][c*4+1] = fmaf(p1, v.y, o[1][c*4+1]);
                o[1][c*4+2] = fmaf(p1, v.z, o[1][c*4+2]); o[1][c*4+3] = fmaf(p1, v.w, o[1][c*4+3]);
                o[2][c*4+0] = fmaf(p2, v.x, o[2][c*4+0]); o[2][c*4+1] = fmaf(p2, v.y, o[2][c*4+1]);
                o[2][c*4+2] = fmaf(p2, v.z, o[2][c*4+2]); o[2][c*4+3] = fmaf(p2, v.w, o[2][c*4+3]);
                o[3][c*4+0] = fmaf(p3, v.x, o[3][c*4+0]); o[3][c*4+1] = fmaf(p3, v.y, o[3][c*4+1]);
                o[3][c*4+2] = fmaf(p3, v.z, o[3][c*4+2]); o[3][c*4+3] = fmaf(p3, v.w, o[3][c*4+3]);
            }
        }
    }

#pragma unroll
    for (int i = 0; i < 4; i++) {
        float invl = 1.0f / l[i];
#pragma unroll
        for (int c = 0; c < 16; c++) o[i][c] *= invl;
    }

    __syncthreads();
    float (*O1)[256] = (float(*)[256])&S->Kt[0][0][0];
    if (y == 0) {
#pragma unroll
        for (int i = 0; i < 4; i++)
#pragma unroll
            for (int c = 0; c < 4; c++) {
                float4 w = {o[i][c*4+0], o[i][c*4+1], o[i][c*4+2], o[i][c*4+3]};
                *(float4*)&O1[ty * 4 + i][c * 64 + txk * 4] = w;
            }
    }
    __syncthreads();
    if (y == 1) {
        float lam = g_lam;
#pragma unroll
        for (int i = 0; i < 4; i++) {
            int q = q0 + ty * 4 + i;
            size_t ob = ((size_t)(b * T_ + q) * 8 + h) * 256;
#pragma unroll
            for (int c = 0; c < 4; c++) {
                float4 a = *(const float4*)&O1[ty * 4 + i][c * 64 + txk * 4];
                float4 r = {a.x - lam * o[i][c*4+0], a.y - lam * o[i][c*4+1],
                            a.z - lam * o[i][c*4+2], a.w - lam * o[i][c*4+3]};
                *(float4*)&out[ob + c * 64 + txk * 4] = r;
            }
        }
    }
}

// ---------------- launch ----------------
extern "C" void kernel_launch(void* const* d_in, const int* in_sizes, int n_in,
                              void* d_out, int out_size) {
    const float* x      = (const float*)d_in[0];
    const float* Wq     = (const float*)d_in[1];
    const float* Wk     = (const float*)d_in[2];
    const float* Wv     = (const float*)d_in[3];
    const float* lq1    = (const float*)d_in[4];
    const float* lk1    = (const float*)d_in[5];
    const float* lq2    = (const float*)d_in[6];
    const float* lk2    = (const float*)d_in[7];
    const float* scaler = (const float*)d_in[8];
    float* out = (float*)d_out;

    rope_lam_kernel<<<T_, 64>>>(lq1, lk1, lq2, lk2);
    qkv_gemm<<<1024, 256>>>(x, Wq, Wk, Wv);
    postproc_kernel<<<dim3(64, 24, B_), 256>>>(scaler);

    cudaFuncSetAttribute(diff_attn_kernel, cudaFuncAttributeMaxDynamicSharedMemorySize,
                         (int)sizeof(AttnS));
    diff_attn_kernel<<<dim3(T_ / 32, 8, B_), 256, sizeof(AttnS)>>>(out);
}

// round 4
// speedup vs baseline: 2.6021x; 1.4220x over previous
#include <cuda_runtime.h>
#include <cuda_bf16.h>
#include <math.h>
#include <stdint.h>

#define B_  2
#define T_  2048

// ---------------- scratch ----------------
__device__ float g_Qt[(size_t)B_ * 2 * 8 * 128 * T_];         // [b][y][h][d][t]
__device__ float g_Kt[(size_t)B_ * 2 * 4 * 128 * T_];         // [b][y][kh][d][t]
__device__ float g_V[(size_t)B_ * T_ * 1024];                 // [b*T][vh*256+vd]
__device__ float g_cos[T_ * 64];
__device__ float g_sin[T_ * 64];
__device__ float g_lam;

// ---------------- RoPE table (bf16-rounded) + lambda ----------------
__global__ void rope_lam_kernel(const float* __restrict__ lq1, const float* __restrict__ lk1,
                                const float* __restrict__ lq2, const float* __restrict__ lk2) {
    int t = blockIdx.x;
    int i = threadIdx.x;
    double invf = 1.0 / pow(10000.0, (double)(2 * i) / 128.0);
    float angle = (float)t * (float)invf;
    g_cos[t * 64 + i] = __bfloat162float(__float2bfloat16((float)cos((double)angle)));
    g_sin[t * 64 + i] = __bfloat162float(__float2bfloat16((float)sin((double)angle)));
    if (t == 0 && i == 0) {
        float s1 = 0.f, s2 = 0.f;
        for (int j = 0; j < 64; j++) { s1 += lq1[j] * lk1[j]; s2 += lq2[j] * lk2[j]; }
        g_lam = expf(s1) - expf(s2) + 0.2f;
    }
}

// ---------------- HMMA helpers (base sm_80+ instructions only) ----------------
__device__ __forceinline__ uint32_t smem_u32(const void* p) {
    uint32_t a;
    asm("{ .reg .u64 t; cvta.to.shared.u64 t, %1; cvt.u32.u64 %0, t; }" : "=r"(a) : "l"(p));
    return a;
}
__device__ __forceinline__ void ldm4(uint32_t* r, uint32_t a) {
    asm volatile("ldmatrix.sync.aligned.m8n8.x4.shared.b16 {%0,%1,%2,%3}, [%4];"
                 : "=r"(r[0]), "=r"(r[1]), "=r"(r[2]), "=r"(r[3]) : "r"(a));
}
#define MMA(d, a, b)                                                          \
    asm volatile("mma.sync.aligned.m16n8k16.row.col.f32.bf16.bf16.f32 "       \
                 "{%0,%1,%2,%3}, {%4,%5,%6,%7}, {%8,%9}, {%0,%1,%2,%3};"      \
                 : "+f"(d[0]), "+f"(d[1]), "+f"(d[2]), "+f"(d[3])             \
                 : "r"(a[0]), "r"(a[1]), "r"(a[2]), "r"(a[3]),                \
                   "r"(b[0]), "r"(b[1]))

// swizzled 16B-chunk address within an 8KB [128 rows x 64B] tile
__device__ __forceinline__ uint32_t tchunk(int r, int c) {
    return (uint32_t)(((r >> 1) << 7) + ((((((r & 1) << 2) | c)) ^ ((r >> 1) & 7)) << 4));
}
__device__ __forceinline__ uint32_t pk2(float x, float y) {
    __nv_bfloat162 h;
    h.x = __float2bfloat16(x);
    h.y = __float2bfloat16(y);
    return *reinterpret_cast<uint32_t*>(&h);
}

// ---------------- bf16x3 HMMA QKV GEMM + fused RMS/RoPE epilogue ----------------
// blocks 0..511 Q, 512..767 K, 768..1023 V. 128x128 tile, BK=32, double-buffered.
// stage s (32KB at s*32768): Ah 8K | Al 8K | Bh 8K | Bl 8K
#define GEMM_SMEM (2 * 16896 * 4)

__device__ __forceinline__ void global_fetch(const float* __restrict__ Ag,
                                             const float* __restrict__ Bg,
                                             int kc, int tid, float4* ra, float4* rb) {
#pragma unroll
    for (int it = 0; it < 4; it++) {
        int idx = tid + it * 256;
        int r = idx >> 3, c4 = idx & 7;
        ra[it] = *(const float4*)(Ag + (size_t)r * 2048 + kc * 32 + c4 * 4);
        rb[it] = *(const float4*)(Bg + (size_t)r * 2048 + kc * 32 + c4 * 4);
    }
}
__device__ __forceinline__ void stage_store(char* st, int tid,
                                            const float4* ra, const float4* rb) {
#pragma unroll
    for (int it = 0; it < 4; it++) {
        int idx = tid + it * 256;
        int r = idx >> 3, c4 = idx & 7;
        uint32_t off = tchunk(r, c4 >> 1) + (c4 & 1) * 8;
        float4 v = ra[it];
        uint32_t h0 = pk2(v.x, v.y), h1 = pk2(v.z, v.w);
        __nv_bfloat162* hp = (__nv_bfloat162*)&h0;
        __nv_bfloat162* hq = (__nv_bfloat162*)&h1;
        uint32_t l0 = pk2(v.x - __bfloat162float(hp->x), v.y - __bfloat162float(hp->y));
        uint32_t l1 = pk2(v.z - __bfloat162float(hq->x), v.w - __bfloat162float(hq->y));
        *(uint2*)(st + off)        = make_uint2(h0, h1);
        *(uint2*)(st + 8192 + off) = make_uint2(l0, l1);
        v = rb[it];
        h0 = pk2(v.x, v.y); h1 = pk2(v.z, v.w);
        l0 = pk2(v.x - __bfloat162float(hp->x), v.y - __bfloat162float(hp->y));
        l1 = pk2(v.z - __bfloat162float(hq->x), v.w - __bfloat162float(hq->y));
        *(uint2*)(st + 16384 + off) = make_uint2(h0, h1);
        *(uint2*)(st + 24576 + off) = make_uint2(l0, l1);
    }
}

__global__ __launch_bounds__(256, 1)
void qkv_gemm_tc(const float* __restrict__ x, const float* __restrict__ Wq,
                 const float* __restrict__ Wk, const float* __restrict__ Wv,
                 const float* __restrict__ scaler) {
    extern __shared__ char sm[];
    uint32_t sb = smem_u32(sm);
    int tid = threadIdx.x;
    int wid = tid >> 5, lane = tid & 31;
    int wy = wid >> 1, wx = wid & 1;

    int bid = blockIdx.x;
    const float* Bw; int type, bx, by;
    if (bid < 512)      { Bw = Wq; type = 0; bx = bid & 15; by = bid >> 4; }
    else if (bid < 768) { int u = bid - 512; Bw = Wk; type = 1; bx = u & 7; by = u >> 3; }
    else                { int u = bid - 768; Bw = Wv; type = 2; bx = u & 7; by = u >> 3; }
    int row0 = by * 128, col0 = bx * 128;
    const float* Ag = x  + (size_t)row0 * 2048;
    const float* Bg = Bw + (size_t)col0 * 2048;

    // ldmatrix lane addressing (within-tile), precomputed chunk offsets
    int a_row = (lane & 7) + ((lane >> 3) & 1) * 8;
    int a_ch  = lane >> 4;
    int b_row = (lane & 7) + (lane >> 4) * 8;
    int b_ch  = (lane >> 3) & 1;
    uint32_t aoff[2][2], boff[4][2];
#pragma unroll
    for (int mt = 0; mt < 2; mt++)
#pragma unroll
        for (int ks = 0; ks < 2; ks++)
            aoff[mt][ks] = tchunk(wy * 32 + mt * 16 + a_row, 2 * ks + a_ch);
#pragma unroll
    for (int nb = 0; nb < 4; nb++)
#pragma unroll
        for (int ks = 0; ks < 2; ks++)
            boff[nb][ks] = tchunk(wx * 64 + nb * 16 + b_row, 2 * ks + b_ch);

    float acc[2][8][4];
#pragma unroll
    for (int i = 0; i < 2; i++)
#pragma unroll
        for (int j = 0; j < 8; j++)
#pragma unroll
            for (int k = 0; k < 4; k++) acc[i][j][k] = 0.f;

    float4 ra[4], rb[4];
    global_fetch(Ag, Bg, 0, tid, ra, rb);
    stage_store(sm, tid, ra, rb);
    __syncthreads();

    for (int kc = 0; kc < 64; kc++) {
        int s = kc & 1;
        if (kc < 63) global_fetch(Ag, Bg, kc + 1, tid, ra, rb);
        uint32_t stb = sb + s * 32768;
#pragma unroll
        for (int ks = 0; ks < 2; ks++) {
            uint32_t Ahf[2][4], Alf[2][4], Bhf[8][2], Blf[8][2];
#pragma unroll
            for (int mt = 0; mt < 2; mt++) {
                ldm4(Ahf[mt], stb + aoff[mt][ks]);
                ldm4(Alf[mt], stb + 8192 + aoff[mt][ks]);
            }
#pragma unroll
            for (int nb = 0; nb < 4; nb++) {
                uint32_t r4[4];
                ldm4(r4, stb + 16384 + boff[nb][ks]);
                Bhf[2*nb][0] = r4[0]; Bhf[2*nb][1] = r4[1];
                Bhf[2*nb+1][0] = r4[2]; Bhf[2*nb+1][1] = r4[3];
                ldm4(r4, stb + 24576 + boff[nb][ks]);
                Blf[2*nb][0] = r4[0]; Blf[2*nb][1] = r4[1];
                Blf[2*nb+1][0] = r4[2]; Blf[2*nb+1][1] = r4[3];
            }
#pragma unroll
            for (int mt = 0; mt < 2; mt++)
#pragma unroll
                for (int n = 0; n < 8; n++) {
                    MMA(acc[mt][n], Ahf[mt], Bhf[n]);
                    MMA(acc[mt][n], Ahf[mt], Blf[n]);
                    MMA(acc[mt][n], Alf[mt], Bhf[n]);
                }
        }
        if (kc < 63) {
            stage_store(sm + (s ^ 1) * 32768, tid, ra, rb);
            __syncthreads();
        }
    }
    __syncthreads();   // stages dead; smem becomes epilogue buffers

    // -------- epilogue --------
    float* buf1 = (float*)sm;            // [128][132] row-major (row = output row)
    float* buf2 = buf1 + 128 * 132;      // [128][132] transposed (row = dim)
#pragma unroll
    for (int mt = 0; mt < 2; mt++)
#pragma unroll
        for (int n = 0; n < 8; n++) {
            int r = wy * 32 + mt * 16 + (lane >> 2);
            int c = wx * 64 + n * 8 + (lane & 3) * 2;
            *(float2*)&buf1[r * 132 + c]       = make_float2(acc[mt][n][0], acc[mt][n][1]);
            *(float2*)&buf1[(r + 8) * 132 + c] = make_float2(acc[mt][n][2], acc[mt][n][3]);
        }
    __syncthreads();

    if (type == 2) {
        for (int i = tid; i < 4096; i += 256) {
            int r = i >> 5, c4 = i & 31;
            *(float4*)&g_V[(size_t)(row0 + r) * 1024 + col0 + c4 * 4] =
                *(const float4*)&buf1[r * 132 + c4 * 4];
        }
        return;
    }

    if (tid < 128) {
        int t = (row0 + tid) & (T_ - 1);
        const float* rowp = &buf1[tid * 132];
        float ss = 0.f;
#pragma unroll
        for (int c4 = 0; c4 < 32; c4++) {
            float4 v = *(const float4*)&rowp[c4 * 4];
            ss = fmaf(v.x, v.x, fmaf(v.y, v.y, fmaf(v.z, v.z, fmaf(v.w, v.w, ss))));
        }
        float rn = rsqrtf(ss * (1.0f / 128.0f) + 1.1920929e-07f);
        float f = (type == 0) ? rn * scaler[bx] * logf((float)(t + 1)) * 0.08838834764831845f
                              : rn;
#pragma unroll
        for (int i = 0; i < 64; i++) {
            float c = g_cos[t * 64 + i], s = g_sin[t * 64 + i];
            float x1 = rowp[i], x2 = rowp[i + 64];
            buf2[i * 132 + tid]        = ( x1 * c + x2 * s) * f;
            buf2[(i + 64) * 132 + tid] = (-x1 * s + x2 * c) * f;
        }
    }
    __syncthreads();

    int b = row0 >> 11;
    int t0 = row0 & (T_ - 1);
    float* dst;
    if (type == 0) {
        int y = bx >> 3, hh = bx & 7;
        dst = g_Qt + ((size_t)((b * 2 + y) * 8 + hh) * 128) * T_ + t0;
    } else {
        int y = bx >> 2, kh = bx & 3;
        dst = g_Kt + ((size_t)((b * 2 + y) * 4 + kh) * 128) * T_ + t0;
    }
    for (int i = tid; i < 4096; i += 256) {
        int d = i >> 5, c4 = i & 31;
        *(float4*)(dst + (size_t)d * T_ + c4 * 4) = *(const float4*)&buf2[d * 132 + c4 * 4];
    }
}

// ---------------- differential causal flash attention (unchanged from R2) ----------------
struct AttnS {
    float Qt[2][128][32];
    float Kt[2][128][32];
    float V [32][256];
    float P [2][32][36];
};

__global__ __launch_bounds__(256, 2) void diff_attn_kernel(float* __restrict__ out) {
    extern __shared__ char sraw[];
    AttnS* S = (AttnS*)sraw;
    int tid = threadIdx.x;
    int qt = (gridDim.x - 1) - blockIdx.x;
    int h = blockIdx.y, b = blockIdx.z;
    int y    = tid >> 7;
    int t128 = tid & 127;
    int txk  = t128 & 15;
    int ty   = t128 >> 4;
    int q0 = qt * 32;

    const float* Qb = g_Qt + ((size_t)(b * 2 * 8 + h) * 128) * T_;
    const size_t QYS = (size_t)8 * 128 * T_;
    const float* Kb = g_Kt + ((size_t)(b * 2 * 4 + (h >> 1)) * 128) * T_;
    const size_t KYS = (size_t)4 * 128 * T_;
    const float* Vb = g_V + (size_t)b * T_ * 1024 + (h >> 1) * 256;

    for (int i4 = tid; i4 < 2048; i4 += 256) {
        int yy = i4 >> 10, rem = i4 & 1023;
        int d = rem >> 3, t4 = rem & 7;
        *(float4*)&S->Qt[yy][d][t4 * 4] =
            *(const float4*)(Qb + yy * QYS + (size_t)d * T_ + q0 + t4 * 4);
    }

    float m[4], l[4], o[4][16];
#pragma unroll
    for (int i = 0; i < 4; i++) {
        m[i] = -INFINITY; l[i] = 0.f;
#pragma unroll
        for (int c = 0; c < 16; c++) o[i][c] = 0.f;
    }

    for (int kt = 0; kt <= qt; kt++) {
        __syncthreads();
        int k0 = kt * 32;
        for (int i4 = tid; i4 < 2048; i4 += 256) {
            int yy = i4 >> 10, rem = i4 & 1023;
            int d = rem >> 3, t4 = rem & 7;
            *(float4*)&S->Kt[yy][d][t4 * 4] =
                *(const float4*)(Kb + yy * KYS + (size_t)d * T_ + k0 + t4 * 4);
        }
        for (int i4 = tid; i4 < 2048; i4 += 256) {
            int k = i4 >> 6, c4 = i4 & 63;
            *(float4*)&S->V[k][c4 * 4] = *(const float4*)(Vb + (size_t)(k0 + k) * 1024 + c4 * 4);
        }
        __syncthreads();

        float s[4][2];
#pragma unroll
        for (int i = 0; i < 4; i++) { s[i][0] = 0.f; s[i][1] = 0.f; }
#pragma unroll 8
        for (int d = 0; d < 128; d++) {
            float4 qv = *(const float4*)&S->Qt[y][d][ty * 4];
            float2 kv = *(const float2*)&S->Kt[y][d][txk * 2];
            s[0][0] = fmaf(qv.x, kv.x, s[0][0]); s[0][1] = fmaf(qv.x, kv.y, s[0][1]);
            s[1][0] = fmaf(qv.y, kv.x, s[1][0]); s[1][1] = fmaf(qv.y, kv.y, s[1][1]);
            s[2][0] = fmaf(qv.z, kv.x, s[2][0]); s[2][1] = fmaf(qv.z, kv.y, s[2][1]);
            s[3][0] = fmaf(qv.w, kv.x, s[3][0]); s[3][1] = fmaf(qv.w, kv.y, s[3][1]);
        }
        if (kt == qt) {
#pragma unroll
            for (int i = 0; i < 4; i++)
#pragma unroll
                for (int j = 0; j < 2; j++)
                    if (txk * 2 + j > ty * 4 + i) s[i][j] = -INFINITY;
        }
        float mt[4], ps[4], alpha[4];
#pragma unroll
        for (int i = 0; i < 4; i++) mt[i] = fmaxf(s[i][0], s[i][1]);
#pragma unroll
        for (int off = 8; off; off >>= 1)
#pragma unroll
            for (int i = 0; i < 4; i++)
                mt[i] = fmaxf(mt[i], __shfl_xor_sync(0xffffffffu, mt[i], off));
#pragma unroll
        for (int i = 0; i < 4; i++) {
            float mn = fmaxf(m[i], mt[i]);
            alpha[i] = __expf(m[i] - mn);
            m[i] = mn;
            s[i][0] = __expf(s[i][0] - mn);
            s[i][1] = __expf(s[i][1] - mn);
            ps[i] = s[i][0] + s[i][1];
        }
#pragma unroll
        for (int off = 8; off; off >>= 1)
#pragma unroll
            for (int i = 0; i < 4; i++)
                ps[i] += __shfl_xor_sync(0xffffffffu, ps[i], off);
#pragma unroll
        for (int i = 0; i < 4; i++) {
            l[i] = l[i] * alpha[i] + ps[i];
            *(float2*)&S->P[y][ty * 4 + i][txk * 2] = make_float2(s[i][0], s[i][1]);
#pragma unroll
            for (int c = 0; c < 16; c++) o[i][c] *= alpha[i];
        }
        __syncwarp();
#pragma unroll 4
        for (int k = 0; k < 32; k++) {
            float p0 = S->P[y][ty * 4 + 0][k];
            float p1 = S->P[y][ty * 4 + 1][k];
            float p2 = S->P[y][ty * 4 + 2][k];
            float p3 = S->P[y][ty * 4 + 3][k];
#pragma unroll
            for (int c = 0; c < 4; c++) {
                float4 v = *(const float4*)&S->V[k][c * 64 + txk * 4];
                o[0][c*4+0] = fmaf(p0, v.x, o[0][c*4+0]); o[0][c*4+1] = fmaf(p0, v.y, o[0][c*4+1]);
                o[0][c*4+2] = fmaf(p0, v.z, o[0][c*4+2]); o[0][c*4+3] = fmaf(p0, v.w, o[0][c*4+3]);
                o[1][c*4+0] = fmaf(p1, v.x, o[1][c*4+0]); o[1][c*4+1] = fmaf(p1, v.y, o[1][c*4+1]);
                o[1][c*4+2] = fmaf(p1, v.z, o[1][c*4+2]); o[1][c*4+3] = fmaf(p1, v.w, o[1][c*4+3]);
                o[2][c*4+0] = fmaf(p2, v.x, o[2][c*4+0]); o[2][c*4+1] = fmaf(p2, v.y, o[2][c*4+1]);
                o[2][c*4+2] = fmaf(p2, v.z, o[2][c*4+2]); o[2][c*4+3] = fmaf(p2, v.w, o[2][c*4+3]);
                o[3][c*4+0] = fmaf(p3, v.x, o[3][c*4+0]); o[3][c*4+1] = fmaf(p3, v.y, o[3][c*4+1]);
                o[3][c*4+2] = fmaf(p3, v.z, o[3][c*4+2]); o[3][c*4+3] = fmaf(p3, v.w, o[3][c*4+3]);
            }
        }
    }

#pragma unroll
    for (int i = 0; i < 4; i++) {
        float invl = 1.0f / l[i];
#pragma unroll
        for (int c = 0; c < 16; c++) o[i][c] *= invl;
    }

    __syncthreads();
    float (*O1)[256] = (float(*)[256])&S->Kt[0][0][0];
    if (y == 0) {
#pragma unroll
        for (int i = 0; i < 4; i++)
#pragma unroll
            for (int c = 0; c < 4; c++) {
                float4 w = {o[i][c*4+0], o[i][c*4+1], o[i][c*4+2], o[i][c*4+3]};
                *(float4*)&O1[ty * 4 + i][c * 64 + txk * 4] = w;
            }
    }
    __syncthreads();
    if (y == 1) {
        float lam = g_lam;
#pragma unroll
        for (int i = 0; i < 4; i++) {
            int q = q0 + ty * 4 + i;
            size_t ob = ((size_t)(b * T_ + q) * 8 + h) * 256;
#pragma unroll
            for (int c = 0; c < 4; c++) {
                float4 a = *(const float4*)&O1[ty * 4 + i][c * 64 + txk * 4];
                float4 r = {a.x - lam * o[i][c*4+0], a.y - lam * o[i][c*4+1],
                            a.z - lam * o[i][c*4+2], a.w - lam * o[i][c*4+3]};
                *(float4*)&out[ob + c * 64 + txk * 4] = r;
            }
        }
    }
}

// ---------------- launch ----------------
extern "C" void kernel_launch(void* const* d_in, const int* in_sizes, int n_in,
                              void* d_out, int out_size) {
    const float* x      = (const float*)d_in[0];
    const float* Wq     = (const float*)d_in[1];
    const float* Wk     = (const float*)d_in[2];
    const float* Wv     = (const float*)d_in[3];
    const float* lq1    = (const float*)d_in[4];
    const float* lk1    = (const float*)d_in[5];
    const float* lq2    = (const float*)d_in[6];
    const float* lk2    = (const float*)d_in[7];
    const float* scaler = (const float*)d_in[8];
    float* out = (float*)d_out;

    rope_lam_kernel<<<T_, 64>>>(lq1, lk1, lq2, lk2);

    cudaFuncSetAttribute(qkv_gemm_tc, cudaFuncAttributeMaxDynamicSharedMemorySize, GEMM_SMEM);
    qkv_gemm_tc<<<1024, 256, GEMM_SMEM>>>(x, Wq, Wk, Wv, scaler);

    cudaFuncSetAttribute(diff_attn_kernel, cudaFuncAttributeMaxDynamicSharedMemorySize,
                         (int)sizeof(AttnS));
    diff_attn_kernel<<<dim3(T_ / 32, 8, B_), 256, sizeof(AttnS)>>>(out);
}

// round 5
// speedup vs baseline: 4.6893x; 1.8021x over previous
#include <cuda_runtime.h>
#include <cuda_bf16.h>
#include <math.h>
#include <stdint.h>

#define B_  2
#define T_  2048
typedef __nv_bfloat16 bf16;

// ---------------- scratch ----------------
__device__ bf16 g_Qh[(size_t)B_ * 2 * 8 * T_ * 128];   // [b][y][h][t][d] hi
__device__ bf16 g_Ql[(size_t)B_ * 2 * 8 * T_ * 128];   // lo
__device__ bf16 g_Kh[(size_t)B_ * 2 * 4 * T_ * 128];   // [b][y][kh][t][d]
__device__ bf16 g_Kl[(size_t)B_ * 2 * 4 * T_ * 128];
__device__ bf16 g_Vh[(size_t)B_ * T_ * 1024];          // [b*t][vh*256+vd]
__device__ bf16 g_Vl[(size_t)B_ * T_ * 1024];
__device__ float g_cos[T_ * 64];
__device__ float g_sin[T_ * 64];
__device__ float g_lam;

// ---------------- RoPE table (f64, bf16-rounded like reference) + lambda ----------------
__global__ void rope_lam_kernel(const float* __restrict__ lq1, const float* __restrict__ lk1,
                                const float* __restrict__ lq2, const float* __restrict__ lk2) {
    int t = blockIdx.x;
    int i = threadIdx.x;
    double invf = 1.0 / pow(10000.0, (double)(2 * i) / 128.0);
    float angle = (float)t * (float)invf;
    g_cos[t * 64 + i] = __bfloat162float(__float2bfloat16((float)cos((double)angle)));
    g_sin[t * 64 + i] = __bfloat162float(__float2bfloat16((float)sin((double)angle)));
    if (t == 0 && i == 0) {
        float s1 = 0.f, s2 = 0.f;
        for (int j = 0; j < 64; j++) { s1 += lq1[j] * lk1[j]; s2 += lq2[j] * lk2[j]; }
        g_lam = expf(s1) - expf(s2) + 0.2f;
    }
}

// ---------------- common HMMA helpers ----------------
__device__ __forceinline__ uint32_t smem_u32(const void* p) {
    uint32_t a;
    asm("{ .reg .u64 t; cvta.to.shared.u64 t, %1; cvt.u32.u64 %0, t; }" : "=r"(a) : "l"(p));
    return a;
}
__device__ __forceinline__ void ldm4(uint32_t* r, uint32_t a) {
    asm volatile("ldmatrix.sync.aligned.m8n8.x4.shared.b16 {%0,%1,%2,%3}, [%4];"
                 : "=r"(r[0]), "=r"(r[1]), "=r"(r[2]), "=r"(r[3]) : "r"(a));
}
__device__ __forceinline__ void ldm4t(uint32_t* r, uint32_t a) {
    asm volatile("ldmatrix.sync.aligned.m8n8.x4.trans.shared.b16 {%0,%1,%2,%3}, [%4];"
                 : "=r"(r[0]), "=r"(r[1]), "=r"(r[2]), "=r"(r[3]) : "r"(a));
}
#define MMA(d, a, b)                                                          \
    asm volatile("mma.sync.aligned.m16n8k16.row.col.f32.bf16.bf16.f32 "       \
                 "{%0,%1,%2,%3}, {%4,%5,%6,%7}, {%8,%9}, {%0,%1,%2,%3};"      \
                 : "+f"(d[0]), "+f"(d[1]), "+f"(d[2]), "+f"(d[3])             \
                 : "r"(a[0]), "r"(a[1]), "r"(a[2]), "r"(a[3]),                \
                   "r"(b[0]), "r"(b[1]))
#define CP16(dst, src)                                                        \
    asm volatile("cp.async.cg.shared.global [%0], [%1], 16;" :: "r"(dst), "l"(src))
#define CP_COMMIT() asm volatile("cp.async.commit_group;" ::: "memory")
#define CP_WAIT(n)  asm volatile("cp.async.wait_group %0;" :: "n"(n) : "memory")

// swizzled 16B-chunk address within a [rows x 64B] tile (rows even count)
__device__ __forceinline__ uint32_t tchunk(int r, int c) {
    return (uint32_t)(((r >> 1) << 7) + ((((((r & 1) << 2) | c)) ^ ((r >> 1) & 7)) << 4));
}
__device__ __forceinline__ uint32_t pk2(float x, float y) {
    __nv_bfloat162 h;
    h.x = __float2bfloat16(x);
    h.y = __float2bfloat16(y);
    return *reinterpret_cast<uint32_t*>(&h);
}
__device__ __forceinline__ void packhl(float x, float y, uint32_t& hi, uint32_t& lo) {
    bf16 hx = __float2bfloat16(x), hy = __float2bfloat16(y);
    __nv_bfloat162 h; h.x = hx; h.y = hy;
    hi = *reinterpret_cast<uint32_t*>(&h);
    lo = pk2(x - __bfloat162float(hx), y - __bfloat162float(hy));
}

// ---------------- bf16x3 HMMA QKV GEMM + fused RMS/RoPE epilogue ----------------
#define GEMM_SMEM (2 * 16896 * 4)

__device__ __forceinline__ void global_fetch(const float* __restrict__ Ag,
                                             const float* __restrict__ Bg,
                                             int kc, int tid, float4* ra, float4* rb) {
#pragma unroll
    for (int it = 0; it < 4; it++) {
        int idx = tid + it * 256;
        int r = idx >> 3, c4 = idx & 7;
        ra[it] = *(const float4*)(Ag + (size_t)r * 2048 + kc * 32 + c4 * 4);
        rb[it] = *(const float4*)(Bg + (size_t)r * 2048 + kc * 32 + c4 * 4);
    }
}
__device__ __forceinline__ void stage_store(char* st, int tid,
                                            const float4* ra, const float4* rb) {
#pragma unroll
    for (int it = 0; it < 4; it++) {
        int idx = tid + it * 256;
        int r = idx >> 3, c4 = idx & 7;
        uint32_t off = tchunk(r, c4 >> 1) + (c4 & 1) * 8;
        float4 v = ra[it];
        uint32_t h0, l0, h1, l1;
        packhl(v.x, v.y, h0, l0); packhl(v.z, v.w, h1, l1);
        *(uint2*)(st + off)        = make_uint2(h0, h1);
        *(uint2*)(st + 8192 + off) = make_uint2(l0, l1);
        v = rb[it];
        packhl(v.x, v.y, h0, l0); packhl(v.z, v.w, h1, l1);
        *(uint2*)(st + 16384 + off) = make_uint2(h0, h1);
        *(uint2*)(st + 24576 + off) = make_uint2(l0, l1);
    }
}

__global__ __launch_bounds__(256, 1)
void qkv_gemm_tc(const float* __restrict__ x, const float* __restrict__ Wq,
                 const float* __restrict__ Wk, const float* __restrict__ Wv,
                 const float* __restrict__ scaler) {
    extern __shared__ char sm[];
    uint32_t sb = smem_u32(sm);
    int tid = threadIdx.x;
    int wid = tid >> 5, lane = tid & 31;
    int wy = wid >> 1, wx = wid & 1;

    int bid = blockIdx.x;
    const float* Bw; int type, bx, by;
    if (bid < 512)      { Bw = Wq; type = 0; bx = bid & 15; by = bid >> 4; }
    else if (bid < 768) { int u = bid - 512; Bw = Wk; type = 1; bx = u & 7; by = u >> 3; }
    else                { int u = bid - 768; Bw = Wv; type = 2; bx = u & 7; by = u >> 3; }
    int row0 = by * 128, col0 = bx * 128;
    const float* Ag = x  + (size_t)row0 * 2048;
    const float* Bg = Bw + (size_t)col0 * 2048;

    int a_row = (lane & 7) + ((lane >> 3) & 1) * 8;
    int a_ch  = lane >> 4;
    int b_row = (lane & 7) + (lane >> 4) * 8;
    int b_ch  = (lane >> 3) & 1;
    uint32_t aoff[2][2], boff[4][2];
#pragma unroll
    for (int mt = 0; mt < 2; mt++)
#pragma unroll
        for (int ks = 0; ks < 2; ks++)
            aoff[mt][ks] = tchunk(wy * 32 + mt * 16 + a_row, 2 * ks + a_ch);
#pragma unroll
    for (int nb = 0; nb < 4; nb++)
#pragma unroll
        for (int ks = 0; ks < 2; ks++)
            boff[nb][ks] = tchunk(wx * 64 + nb * 16 + b_row, 2 * ks + b_ch);

    float acc[2][8][4];
#pragma unroll
    for (int i = 0; i < 2; i++)
#pragma unroll
        for (int j = 0; j < 8; j++)
#pragma unroll
            for (int k = 0; k < 4; k++) acc[i][j][k] = 0.f;

    float4 ra[4], rb[4];
    global_fetch(Ag, Bg, 0, tid, ra, rb);
    stage_store(sm, tid, ra, rb);
    __syncthreads();

    for (int kc = 0; kc < 64; kc++) {
        int s = kc & 1;
        if (kc < 63) global_fetch(Ag, Bg, kc + 1, tid, ra, rb);
        uint32_t stb = sb + s * 32768;
#pragma unroll
        for (int ks = 0; ks < 2; ks++) {
            uint32_t Ahf[2][4], Alf[2][4], Bhf[8][2], Blf[8][2];
#pragma unroll
            for (int mt = 0; mt < 2; mt++) {
                ldm4(Ahf[mt], stb + aoff[mt][ks]);
                ldm4(Alf[mt], stb + 8192 + aoff[mt][ks]);
            }
#pragma unroll
            for (int nb = 0; nb < 4; nb++) {
                uint32_t r4[4];
                ldm4(r4, stb + 16384 + boff[nb][ks]);
                Bhf[2*nb][0] = r4[0]; Bhf[2*nb][1] = r4[1];
                Bhf[2*nb+1][0] = r4[2]; Bhf[2*nb+1][1] = r4[3];
                ldm4(r4, stb + 24576 + boff[nb][ks]);
                Blf[2*nb][0] = r4[0]; Blf[2*nb][1] = r4[1];
                Blf[2*nb+1][0] = r4[2]; Blf[2*nb+1][1] = r4[3];
            }
#pragma unroll
            for (int mt = 0; mt < 2; mt++)
#pragma unroll
                for (int n = 0; n < 8; n++) {
                    MMA(acc[mt][n], Ahf[mt], Bhf[n]);
                    MMA(acc[mt][n], Ahf[mt], Blf[n]);
                    MMA(acc[mt][n], Alf[mt], Bhf[n]);
                }
        }
        if (kc < 63) {
            stage_store(sm + (s ^ 1) * 32768, tid, ra, rb);
            __syncthreads();
        }
    }
    __syncthreads();

    // -------- epilogue: row-major fp32 to smem, then bf16 hi/lo to gmem --------
    float* buf1 = (float*)sm;   // [128][132]
#pragma unroll
    for (int mt = 0; mt < 2; mt++)
#pragma unroll
        for (int n = 0; n < 8; n++) {
            int r = wy * 32 + mt * 16 + (lane >> 2);
            int c = wx * 64 + n * 8 + (lane & 3) * 2;
            *(float2*)&buf1[r * 132 + c]       = make_float2(acc[mt][n][0], acc[mt][n][1]);
            *(float2*)&buf1[(r + 8) * 132 + c] = make_float2(acc[mt][n][2], acc[mt][n][3]);
        }
    __syncthreads();

    if (type == 2) {
        for (int i = tid; i < 4096; i += 256) {
            int r = i >> 5, c4 = i & 31;
            float4 v = *(const float4*)&buf1[r * 132 + c4 * 4];
            uint32_t h0, l0, h1, l1;
            packhl(v.x, v.y, h0, l0); packhl(v.z, v.w, h1, l1);
            size_t off = (size_t)(row0 + r) * 1024 + col0 + c4 * 4;
            *(uint2*)(g_Vh + off) = make_uint2(h0, h1);
            *(uint2*)(g_Vl + off) = make_uint2(l0, l1);
        }
        return;
    }

    if (tid < 128) {
        int b = row0 >> 11;
        int t = (row0 & (T_ - 1)) + tid;
        const float* rowp = &buf1[tid * 132];
        float ss = 0.f;
#pragma unroll
        for (int c4 = 0; c4 < 32; c4++) {
            float4 v = *(const float4*)&rowp[c4 * 4];
            ss = fmaf(v.x, v.x, fmaf(v.y, v.y, fmaf(v.z, v.z, fmaf(v.w, v.w, ss))));
        }
        float rn = rsqrtf(ss * (1.0f / 128.0f) + 1.1920929e-07f);
        float f = (type == 0) ? rn * scaler[bx] * logf((float)(t + 1)) * 0.08838834764831845f
                              : rn;
        float ov[128];
#pragma unroll
        for (int i = 0; i < 64; i++) {
            float c = g_cos[t * 64 + i], s = g_sin[t * 64 + i];
            float x1 = rowp[i], x2 = rowp[i + 64];
            ov[i]      = ( x1 * c + x2 * s) * f;
            ov[i + 64] = (-x1 * s + x2 * c) * f;
        }
        size_t rbase;
        bf16 *dh, *dl;
        if (type == 0) {
            rbase = ((size_t)((b * 2 + (bx >> 3)) * 8 + (bx & 7)) * T_ + t) * 128;
            dh = g_Qh + rbase; dl = g_Ql + rbase;
        } else {
            rbase = ((size_t)((b * 2 + (bx >> 2)) * 4 + (bx & 3)) * T_ + t) * 128;
            dh = g_Kh + rbase; dl = g_Kl + rbase;
        }
#pragma unroll
        for (int c4 = 0; c4 < 32; c4++) {
            uint32_t h0, l0, h1, l1;
            packhl(ov[c4*4], ov[c4*4+1], h0, l0);
            packhl(ov[c4*4+2], ov[c4*4+3], h1, l1);
            *(uint2*)(dh + c4 * 4) = make_uint2(h0, h1);
            *(uint2*)(dl + c4 * 4) = make_uint2(l0, l1);
        }
    }
}

// ---------------- HMMA differential causal flash attention ----------------
// block = (b, h, 32q); 8 warps = y(2) x qs(2) x vh(2). 32-key tiles, 2-stage cp.async.
// stage s at s*64KB: K planes [(br*2+hl)*4+dg]*2KB (32KB) | V planes hl*16KB (32KB)
#define ATT_SMEM (2 * 65536)

__global__ __launch_bounds__(256, 1) void diff_attn_hmma(float* __restrict__ out) {
    extern __shared__ char sm[];
    uint32_t sb = smem_u32(sm);
    int tid = threadIdx.x, lane = tid & 31, wid = tid >> 5;
    int y = wid >> 2, qs = (wid >> 1) & 1, vh = wid & 1;
    int qt = 63 - blockIdx.x;
    int h = blockIdx.y, b = blockIdx.z;
    int q0 = qt * 32;
    int g = lane >> 2, t2 = (lane & 3) << 1;
    int kh = h >> 1;

    const bf16* Kp[2][2];
    Kp[0][0] = g_Kh + ((size_t)((b * 2 + 0) * 4 + kh) * T_) * 128;
    Kp[0][1] = g_Kl + ((size_t)((b * 2 + 0) * 4 + kh) * T_) * 128;
    Kp[1][0] = g_Kh + ((size_t)((b * 2 + 1) * 4 + kh) * T_) * 128;
    Kp[1][1] = g_Kl + ((size_t)((b * 2 + 1) * 4 + kh) * T_) * 128;
    const bf16* Vp[2];
    Vp[0] = g_Vh + (size_t)b * T_ * 1024 + kh * 256;
    Vp[1] = g_Vl + (size_t)b * T_ * 1024 + kh * 256;

    // ---- stage Q (once) into stage0 K region, extract A-fragments ----
    uint32_t Qh[8][4], Ql[8][4];
    {
        const bf16* Qp[2][2];
        Qp[0][0] = g_Qh + ((size_t)((b * 2 + 0) * 8 + h) * T_ + q0) * 128;
        Qp[0][1] = g_Ql + ((size_t)((b * 2 + 0) * 8 + h) * T_ + q0) * 128;
        Qp[1][0] = g_Qh + ((size_t)((b * 2 + 1) * 8 + h) * T_ + q0) * 128;
        Qp[1][1] = g_Ql + ((size_t)((b * 2 + 1) * 8 + h) * T_ + q0) * 128;
#pragma unroll
        for (int it = 0; it < 8; it++) {
            int i = tid + it * 256;
            int br = i >> 10, hl = (i >> 9) & 1, qq = (i >> 4) & 31, c = i & 15;
            uint4 v = *(const uint4*)(Qp[br][hl] + (size_t)qq * 128 + c * 8);
            *(uint4*)(sm + ((br * 2 + hl) * 4 + (c >> 2)) * 2048 + tchunk(qq, c & 3)) = v;
        }
        __syncthreads();
        int a_row = (lane & 7) + ((lane >> 3) & 1) * 8;
        int a_ch  = lane >> 4;
#pragma unroll
        for (int kc = 0; kc < 8; kc++) {
            uint32_t off = tchunk(qs * 16 + a_row, 2 * (kc & 1) + a_ch);
            ldm4(Qh[kc], sb + ((y * 2 + 0) * 4 + (kc >> 1)) * 2048 + off);
            ldm4(Ql[kc], sb + ((y * 2 + 1) * 4 + (kc >> 1)) * 2048 + off);
        }
        __syncthreads();
    }

    float m0 = -INFINITY, m1 = -INFINITY, l0 = 0.f, l1 = 0.f;
    float oacc[16][4];
#pragma unroll
    for (int n = 0; n < 16; n++)
#pragma unroll
        for (int j = 0; j < 4; j++) oacc[n][j] = 0.f;

    int b_row = (lane & 7) + (lane >> 4) * 8;
    int b_ch  = (lane >> 3) & 1;
    int nt = qt + 1;

    // stage issue
    auto stage_issue = [&](int kt, int s) {
        uint32_t kb = sb + s * 65536;
        uint32_t vb = kb + 32768;
        int k0 = kt * 32;
#pragma unroll
        for (int it = 0; it < 8; it++) {
            int i = tid + it * 256;
            int br = i >> 10, hl = (i >> 9) & 1, kk = (i >> 4) & 31, c = i & 15;
            const bf16* src = Kp[br][hl] + (size_t)(k0 + kk) * 128 + c * 8;
            CP16(kb + ((br * 2 + hl) * 4 + (c >> 2)) * 2048 + tchunk(kk, c & 3), src);
        }
#pragma unroll
        for (int it = 0; it < 8; it++) {
            int i = tid + it * 256;
            int hl = i >> 10, kk = (i >> 5) & 31, c = i & 31;
            const bf16* src = Vp[hl] + (size_t)(k0 + kk) * 1024 + c * 8;
            CP16(vb + hl * 16384 + kk * 512 + ((c ^ (kk & 7)) << 4), src);
        }
        CP_COMMIT();
    };

    stage_issue(0, 0);
    for (int kt = 0; kt < nt; kt++) {
        if (kt + 1 < nt) { stage_issue(kt + 1, (kt + 1) & 1); CP_WAIT(1); }
        else             { CP_WAIT(0); }
        __syncthreads();
        uint32_t kb = sb + (kt & 1) * 65536;
        uint32_t vb = kb + 32768;
        int k0 = kt * 32;

        // ---- S = Q K^T ----
        float sacc[4][4];
#pragma unroll
        for (int n = 0; n < 4; n++)
#pragma unroll
            for (int j = 0; j < 4; j++) sacc[n][j] = 0.f;
#pragma unroll
        for (int kc = 0; kc < 8; kc++) {
            uint32_t ph_ = kb + ((y * 2 + 0) * 4 + (kc >> 1)) * 2048;
            uint32_t pl_ = kb + ((y * 2 + 1) * 4 + (kc >> 1)) * 2048;
            int ks = kc & 1;
            uint32_t bh[4][2], bl[4][2];
#pragma unroll
            for (int nb = 0; nb < 2; nb++) {
                uint32_t off = tchunk(nb * 16 + b_row, 2 * ks + b_ch);
                uint32_t r4[4];
                ldm4(r4, ph_ + off);
                bh[2*nb][0] = r4[0]; bh[2*nb][1] = r4[1];
                bh[2*nb+1][0] = r4[2]; bh[2*nb+1][1] = r4[3];
                ldm4(r4, pl_ + off);
                bl[2*nb][0] = r4[0]; bl[2*nb][1] = r4[1];
                bl[2*nb+1][0] = r4[2]; bl[2*nb+1][1] = r4[3];
            }
#pragma unroll
            for (int n = 0; n < 4; n++) {
                MMA(sacc[n], Qh[kc], bh[n]);
                MMA(sacc[n], Qh[kc], bl[n]);
                MMA(sacc[n], Ql[kc], bh[n]);
            }
        }
        // ---- causal mask (diagonal tile only) ----
        if (kt == qt) {
            int r0 = q0 + qs * 16 + g, r1 = r0 + 8;
#pragma unroll
            for (int n = 0; n < 4; n++) {
                int c = k0 + n * 8 + t2;
                if (c     > r0) sacc[n][0] = -INFINITY;
                if (c + 1 > r0) sacc[n][1] = -INFINITY;
                if (c     > r1) sacc[n][2] = -INFINITY;
                if (c + 1 > r1) sacc[n][3] = -INFINITY;
            }
        }
        // ---- online softmax ----
        float mx0 = -INFINITY, mx1 = -INFINITY;
#pragma unroll
        for (int n = 0; n < 4; n++) {
            mx0 = fmaxf(mx0, fmaxf(sacc[n][0], sacc[n][1]));
            mx1 = fmaxf(mx1, fmaxf(sacc[n][2], sacc[n][3]));
        }
        mx0 = fmaxf(mx0, __shfl_xor_sync(0xffffffffu, mx0, 1));
        mx0 = fmaxf(mx0, __shfl_xor_sync(0xffffffffu, mx0, 2));
        mx1 = fmaxf(mx1, __shfl_xor_sync(0xffffffffu, mx1, 1));
        mx1 = fmaxf(mx1, __shfl_xor_sync(0xffffffffu, mx1, 2));
        float mn0 = fmaxf(m0, mx0), mn1 = fmaxf(m1, mx1);
        float a0 = __expf(m0 - mn0), a1 = __expf(m1 - mn1);
        m0 = mn0; m1 = mn1;
        float s0 = 0.f, s1 = 0.f;
#pragma unroll
        for (int n = 0; n < 4; n++) {
            sacc[n][0] = __expf(sacc[n][0] - mn0); s0 += sacc[n][0];
            sacc[n][1] = __expf(sacc[n][1] - mn0); s0 += sacc[n][1];
            sacc[n][2] = __expf(sacc[n][2] - mn1); s1 += sacc[n][2];
            sacc[n][3] = __expf(sacc[n][3] - mn1); s1 += sacc[n][3];
        }
        s0 += __shfl_xor_sync(0xffffffffu, s0, 1);
        s0 += __shfl_xor_sync(0xffffffffu, s0, 2);
        s1 += __shfl_xor_sync(0xffffffffu, s1, 1);
        s1 += __shfl_xor_sync(0xffffffffu, s1, 2);
        l0 = l0 * a0 + s0;
        l1 = l1 * a1 + s1;
#pragma unroll
        for (int n = 0; n < 16; n++) {
            oacc[n][0] *= a0; oacc[n][1] *= a0;
            oacc[n][2] *= a1; oacc[n][3] *= a1;
        }
        // ---- O += P V ----
#pragma unroll
        for (int kk = 0; kk < 2; kk++) {
            uint32_t pha[4], pla[4];
            packhl(sacc[2*kk][0],   sacc[2*kk][1],   pha[0], pla[0]);
            packhl(sacc[2*kk][2],   sacc[2*kk][3],   pha[1], pla[1]);
            packhl(sacc[2*kk+1][0], sacc[2*kk+1][1], pha[2], pla[2]);
            packhl(sacc[2*kk+1][2], sacc[2*kk+1][3], pha[3], pla[3]);
            int krow = kk * 16 + (lane & 15);
            uint32_t rowadr = (uint32_t)(krow * 512);
            int swz = krow & 7;
#pragma unroll
            for (int ng = 0; ng < 8; ng++) {
                int lch = vh * 16 + ng * 2 + (lane >> 4);
                uint32_t ah = vb + rowadr + (uint32_t)((lch ^ swz) << 4);
                uint32_t r4[4];
                ldm4t(r4, ah);
                uint32_t bvh0[2] = {r4[0], r4[1]}, bvh1[2] = {r4[2], r4[3]};
                ldm4t(r4, ah + 16384);
                uint32_t bvl0[2] = {r4[0], r4[1]}, bvl1[2] = {r4[2], r4[3]};
                MMA(oacc[2*ng],   pha, bvh0);
                MMA(oacc[2*ng],   pha, bvl0);
                MMA(oacc[2*ng],   pla, bvh0);
                MMA(oacc[2*ng+1], pha, bvh1);
                MMA(oacc[2*ng+1], pha, bvl1);
                MMA(oacc[2*ng+1], pla, bvh1);
            }
        }
        __syncthreads();
    }

    // ---- epilogue: normalize, combine branches, write ----
    float i0 = 1.f / l0, i1 = 1.f / l1;
    float* Ob = (float*)sm + y * 8192;     // [32][256]
#pragma unroll
    for (int n = 0; n < 16; n++) {
        int col = vh * 128 + n * 8 + t2;
        int r = qs * 16 + g;
        Ob[r * 256 + col]           = oacc[n][0] * i0;
        Ob[r * 256 + col + 1]       = oacc[n][1] * i0;
        Ob[(r + 8) * 256 + col]     = oacc[n][2] * i1;
        Ob[(r + 8) * 256 + col + 1] = oacc[n][3] * i1;
    }
    __syncthreads();
    float lam = g_lam;
    float* O0 = (float*)sm;
    float* O1 = (float*)sm + 8192;
    for (int i = tid; i < 2048; i += 256) {
        int r = i >> 6, c4 = i & 63;
        float4 v1 = *(const float4*)&O0[r * 256 + c4 * 4];
        float4 v2 = *(const float4*)&O1[r * 256 + c4 * 4];
        float4 o = {v1.x - lam * v2.x, v1.y - lam * v2.y,
                    v1.z - lam * v2.z, v1.w - lam * v2.w};
        *(float4*)&out[((size_t)(b * T_ + q0 + r) * 8 + h) * 256 + c4 * 4] = o;
    }
}

// ---------------- launch ----------------
extern "C" void kernel_launch(void* const* d_in, const int* in_sizes, int n_in,
                              void* d_out, int out_size) {
    const float* x      = (const float*)d_in[0];
    const float* Wq     = (const float*)d_in[1];
    const float* Wk     = (const float*)d_in[2];
    const float* Wv     = (const float*)d_in[3];
    const float* lq1    = (const float*)d_in[4];
    const float* lk1    = (const float*)d_in[5];
    const float* lq2    = (const float*)d_in[6];
    const float* lk2    = (const float*)d_in[7];
    const float* scaler = (const float*)d_in[8];
    float* out = (float*)d_out;

    rope_lam_kernel<<<T_, 64>>>(lq1, lk1, lq2, lk2);

    cudaFuncSetAttribute(qkv_gemm_tc, cudaFuncAttributeMaxDynamicSharedMemorySize, GEMM_SMEM);
    qkv_gemm_tc<<<1024, 256, GEMM_SMEM>>>(x, Wq, Wk, Wv, scaler);

    cudaFuncSetAttribute(diff_attn_hmma, cudaFuncAttributeMaxDynamicSharedMemorySize, ATT_SMEM);
    diff_attn_hmma<<<dim3(64, 8, B_), 256, ATT_SMEM>>>(out);
}